// round 6
// baseline (speedup 1.0000x reference)
#include <cuda_runtime.h>
#include <cuda_bf16.h>
#include <stdint.h>

#define N_NODES  100000
#define N_EDGES  1600000
#define D        128
#define N_LAYERS 7
#define N_GRAPHS 64
#define N_CLASSES 10
#define SNN_IN   512
#define SNN_H    1024

// ---------------- device scratch (no allocations allowed) ----------------
__device__ __align__(16) float g_bufA[(size_t)N_NODES * D];
__device__ __align__(16) float g_bufB[(size_t)N_NODES * D];
__device__ __align__(16) float g_agg [(size_t)N_NODES * D];

__device__ int   g_cnt   [N_NODES];
__device__ int   g_rowptr[N_NODES + 1];
__device__ int   g_cursor[N_NODES];
__device__ int   g_col   [N_EDGES];

__device__ float g_pool[N_GRAPHS * D];
__device__ float g_cnts[N_GRAPHS];
__device__ float g_snnh[N_GRAPHS * SNN_H];

__device__ int   g_is64;   // 1 if index inputs are int64, 0 if int32

// ---------------- dtype detection ----------------
// If edge_index is int64 (values < 2^31), every odd int32 word is 0.
// If int32, odd words are random node ids in [0, N_NODES) — P(all 128 zero) ~ 0.
__global__ void detect_kernel(const int* __restrict__ ei32) {
    if (threadIdx.x == 0 && blockIdx.x == 0) {
        int orr = 0;
        #pragma unroll 8
        for (int i = 1; i < 256; i += 2) orr |= ei32[i];
        g_is64 = (orr == 0) ? 1 : 0;
    }
}

__device__ __forceinline__ int idx_at(const void* __restrict__ p, long long i, int is64) {
    long long v = is64 ? ((const long long*)p)[i] : (long long)((const int*)p)[i];
    return (int)v;
}
__device__ __forceinline__ int clampi(int v, int lo, int hi) {
    return v < lo ? lo : (v > hi ? hi : v);
}

// ---------------- helpers ----------------
__global__ void copyin_kernel(const float* __restrict__ x) {
    size_t i = (size_t)blockIdx.x * blockDim.x + threadIdx.x;
    size_t n4 = (size_t)N_NODES * D / 4;
    if (i < n4) ((float4*)g_bufB)[i] = ((const float4*)x)[i];
}

__global__ void zero_kernel() {
    int i = blockIdx.x * blockDim.x + threadIdx.x;
    if (i < N_NODES) g_cnt[i] = 0;
    if (i < N_GRAPHS * D) g_pool[i] = 0.f;
    if (i < N_GRAPHS) g_cnts[i] = 0.f;
}

__global__ void hist_kernel(const void* __restrict__ ei) {
    int e = blockIdx.x * blockDim.x + threadIdx.x;
    if (e >= N_EDGES) return;
    int is64 = g_is64;
    int dst = clampi(idx_at(ei, (long long)N_EDGES + e, is64), 0, N_NODES - 1);
    atomicAdd(&g_cnt[dst], 1);
}

// single-block exclusive scan over g_cnt -> g_rowptr / g_cursor
__global__ void scan_kernel() {
    __shared__ int sh[1024];
    __shared__ int s_carry;
    int tid = threadIdx.x;
    if (tid == 0) { s_carry = 0; g_rowptr[0] = 0; }
    __syncthreads();
    for (int base = 0; base < N_NODES; base += 1024) {
        int i = base + tid;
        int v = (i < N_NODES) ? g_cnt[i] : 0;
        sh[tid] = v;
        __syncthreads();
        for (int off = 1; off < 1024; off <<= 1) {
            int t = (tid >= off) ? sh[tid - off] : 0;
            __syncthreads();
            sh[tid] += t;
            __syncthreads();
        }
        int incl  = sh[tid];
        int carry = s_carry;
        if (i < N_NODES) {
            g_cursor[i]     = carry + incl - v;   // exclusive
            g_rowptr[i + 1] = carry + incl;       // inclusive
        }
        __syncthreads();
        if (tid == 0) s_carry = carry + sh[1023];
        __syncthreads();
    }
}

__global__ void scatter_kernel(const void* __restrict__ ei) {
    int e = blockIdx.x * blockDim.x + threadIdx.x;
    if (e >= N_EDGES) return;
    int is64 = g_is64;
    int src = clampi(idx_at(ei, e, is64),                      0, N_NODES - 1);
    int dst = clampi(idx_at(ei, (long long)N_EDGES + e, is64), 0, N_NODES - 1);
    int pos = atomicAdd(&g_cursor[dst], 1);
    if (pos >= 0 && pos < N_EDGES) g_col[pos] = src;
}

// ---------------- per-layer aggregation: warp per node, float4 per lane ----
// in_sel: 0 -> g_bufB, 1 -> g_bufA
__global__ void agg_kernel(int in_sel) {
    const float* __restrict__ h = in_sel ? g_bufA : g_bufB;
    int warp = (blockIdx.x * blockDim.x + threadIdx.x) >> 5;
    int lane = threadIdx.x & 31;
    if (warp >= N_NODES) return;
    int s = g_rowptr[warp];
    int e = g_rowptr[warp + 1];
    float4 acc = make_float4(0.f, 0.f, 0.f, 0.f);
    for (int i = s; i < e; i++) {
        int src = g_col[i];
        float4 v = *(const float4*)(h + (size_t)src * D + lane * 4);
        acc.x += v.x; acc.y += v.y; acc.z += v.z; acc.w += v.w;
    }
    *(float4*)(g_agg + (size_t)warp * D + lane * 4) = acc;
}

// ---------------- fused GraphConv GEMM ----------------
// out = relu(agg @ Wrel + cur @ Wroot + brel), M=100000, N=128, K=128(+128)
#define BM 64
#define BK 32
__global__ __launch_bounds__(256) void gemm_kernel(
    int in_sel,
    const float* __restrict__ wrel, const float* __restrict__ wroot,
    const float* __restrict__ brel)
{
    const float* __restrict__ cur = in_sel ? g_bufA : g_bufB;
    float* __restrict__ out       = in_sel ? g_bufB : g_bufA;
    const float* __restrict__ agg = g_agg;

    __shared__ float sWrel[BK][D];     // 16 KB
    __shared__ float sWroot[BK][D];    // 16 KB
    __shared__ float sAagg[BM][BK];    // 8 KB
    __shared__ float sAcur[BM][BK];    // 8 KB

    int tx = threadIdx.x;
    int nt = tx & 31;        // column group: cols nt*4 .. nt*4+3
    int mt = tx >> 5;        // row group:   rows mt*8 .. mt*8+7 (warp-uniform)
    int m0 = blockIdx.x * BM;

    float4 acc[8];
    #pragma unroll
    for (int r = 0; r < 8; r++) acc[r] = make_float4(0.f, 0.f, 0.f, 0.f);

    for (int k0 = 0; k0 < D; k0 += BK) {
        #pragma unroll
        for (int i = 0; i < 4; i++) {
            int idx = tx + i * 256;              // 1024 float4 total
            int kk = idx >> 5, cq = idx & 31;
            *(float4*)&sWrel [kk][cq * 4] = *(const float4*)(wrel  + (size_t)(k0 + kk) * D + cq * 4);
            *(float4*)&sWroot[kk][cq * 4] = *(const float4*)(wroot + (size_t)(k0 + kk) * D + cq * 4);
        }
        #pragma unroll
        for (int i = 0; i < 2; i++) {
            int idx = tx + i * 256;
            int row = idx >> 3, cq = idx & 7;    // 8 float4 per row
            int m = m0 + row;
            float4 va = make_float4(0.f,0.f,0.f,0.f), vc = va;
            if (m < N_NODES) {
                va = *(const float4*)(agg + (size_t)m * D + k0 + cq * 4);
                vc = *(const float4*)(cur + (size_t)m * D + k0 + cq * 4);
            }
            *(float4*)&sAagg[row][cq * 4] = va;
            *(float4*)&sAcur[row][cq * 4] = vc;
        }
        __syncthreads();

        #pragma unroll 4
        for (int kk = 0; kk < BK; kk++) {
            float4 wr = *(float4*)&sWrel [kk][nt * 4];
            float4 wo = *(float4*)&sWroot[kk][nt * 4];
            #pragma unroll
            for (int r = 0; r < 8; r++) {
                float a1 = sAagg[mt * 8 + r][kk];
                float a2 = sAcur[mt * 8 + r][kk];
                acc[r].x = fmaf(a1, wr.x, acc[r].x);
                acc[r].y = fmaf(a1, wr.y, acc[r].y);
                acc[r].z = fmaf(a1, wr.z, acc[r].z);
                acc[r].w = fmaf(a1, wr.w, acc[r].w);
                acc[r].x = fmaf(a2, wo.x, acc[r].x);
                acc[r].y = fmaf(a2, wo.y, acc[r].y);
                acc[r].z = fmaf(a2, wo.z, acc[r].z);
                acc[r].w = fmaf(a2, wo.w, acc[r].w);
            }
        }
        __syncthreads();
    }

    float4 b = *(const float4*)(brel + nt * 4);
    #pragma unroll
    for (int r = 0; r < 8; r++) {
        int m = m0 + mt * 8 + r;
        if (m < N_NODES) {
            float4 o;
            o.x = fmaxf(acc[r].x + b.x, 0.f);
            o.y = fmaxf(acc[r].y + b.y, 0.f);
            o.z = fmaxf(acc[r].z + b.z, 0.f);
            o.w = fmaxf(acc[r].w + b.w, 0.f);
            *(float4*)(out + (size_t)m * D + nt * 4) = o;
        }
    }
}

// ---------------- pooling ----------------
#define POOL_CHUNK 512
// final h lives in g_bufA (after 7 layers starting from g_bufB)
__global__ void pool_kernel(const void* __restrict__ batch) {
    const float* __restrict__ h = g_bufA;
    int ch = threadIdx.x;                  // 128
    int start = blockIdx.x * POOL_CHUNK;
    if (start >= N_NODES) return;
    int end = min(start + POOL_CHUNK, N_NODES);
    int is64 = g_is64;
    int cur = clampi(idx_at(batch, start, is64), 0, N_GRAPHS - 1);
    float acc = 0.f;
    for (int i = start; i < end; i++) {
        int b = clampi(idx_at(batch, i, is64), 0, N_GRAPHS - 1);
        if (b != cur) {
            atomicAdd(&g_pool[cur * D + ch], acc);
            acc = 0.f; cur = b;
        }
        acc += h[(size_t)i * D + ch];
    }
    atomicAdd(&g_pool[cur * D + ch], acc);
}

__global__ void count_kernel(const void* __restrict__ batch) {
    int i = blockIdx.x * blockDim.x + threadIdx.x;
    if (i >= N_NODES) return;
    int b = clampi(idx_at(batch, i, g_is64), 0, N_GRAPHS - 1);
    atomicAdd(&g_cnts[b], 1.f);
}

// ---------------- SNN layer 1 ----------------
__global__ void snn1_kernel(const float* __restrict__ x, const float* __restrict__ w1,
                            const float* __restrict__ b1) {
    __shared__ float xs[SNN_IN];
    int g = blockIdx.x;
    for (int i = threadIdx.x; i < SNN_IN; i += 256) xs[i] = x[g * SNN_IN + i];
    __syncthreads();
    #pragma unroll
    for (int j = 0; j < 4; j++) {
        int n = threadIdx.x + j * 256;
        float acc = b1[n];
        for (int k = 0; k < SNN_IN; k++)
            acc = fmaf(xs[k], w1[(size_t)k * SNN_H + n], acc);
        g_snnh[g * SNN_H + n] = fmaxf(acc, 0.f);
    }
}

// ---------------- final head + fusion (one block, 640 threads) -------------
__global__ void head_kernel(const float* __restrict__ w2, const float* __restrict__ b2,
                            const float* __restrict__ linw, const float* __restrict__ linb,
                            const float* __restrict__ fw, const float* __restrict__ fb,
                            float* __restrict__ out) {
    __shared__ float s_snn[N_GRAPHS * N_CLASSES];
    __shared__ float s_gnn[N_GRAPHS * N_CLASSES];
    int t = threadIdx.x;                // 640
    int g = t / N_CLASSES, c = t % N_CLASSES;

    float acc = b2[c];
    for (int k = 0; k < SNN_H; k++)
        acc = fmaf(g_snnh[g * SNN_H + k], w2[k * N_CLASSES + c], acc);
    s_snn[g * N_CLASSES + c] = 0.85f * acc;

    float cnt = fmaxf(g_cnts[g], 1.0f);
    float inv = 1.0f / cnt;
    float acc2 = linb[c];
    for (int k = 0; k < D; k++)
        acc2 = fmaf(g_pool[g * D + k] * inv, linw[k * N_CLASSES + c], acc2);
    s_gnn[g * N_CLASSES + c] = acc2;
    __syncthreads();

    float o = fb[c];
    #pragma unroll
    for (int j = 0; j < N_CLASSES; j++) {
        o = fmaf(s_snn[g * N_CLASSES + j], fw[j * N_CLASSES + c], o);
        o = fmaf(s_gnn[g * N_CLASSES + j], fw[(N_CLASSES + j) * N_CLASSES + c], o);
    }
    out[g * N_CLASSES + c] = o;
}

// ---------------- launch ----------------
extern "C" void kernel_launch(void* const* d_in, const int* in_sizes, int n_in,
                              void* d_out, int out_size) {
    const float* snn_x  = (const float*)d_in[0];
    const float* x      = (const float*)d_in[1];
    const void*  ei     = d_in[2];              // int32 or int64, detected on device
    const void*  batch  = d_in[3];
    const float* snn_w1 = (const float*)d_in[4];
    const float* snn_b1 = (const float*)d_in[5];
    const float* snn_w2 = (const float*)d_in[6];
    const float* snn_b2 = (const float*)d_in[7];
    const float* cwrel  = (const float*)d_in[8];
    const float* cwroot = (const float*)d_in[9];
    const float* cbrel  = (const float*)d_in[10];
    const float* lin_w  = (const float*)d_in[11];
    const float* lin_b  = (const float*)d_in[12];
    const float* fuse_w = (const float*)d_in[13];
    const float* fuse_b = (const float*)d_in[14];
    float* out = (float*)d_out;

    // dtype detection + CSR build + zeroing + input staging
    detect_kernel<<<1, 32>>>((const int*)ei);
    copyin_kernel<<<(N_NODES * D / 4 + 255) / 256, 256>>>(x);
    zero_kernel<<<(N_NODES + 255) / 256, 256>>>();
    hist_kernel<<<(N_EDGES + 255) / 256, 256>>>(ei);
    scan_kernel<<<1, 1024>>>();
    scatter_kernel<<<(N_EDGES + 255) / 256, 256>>>(ei);

    // SNN branch (independent)
    snn1_kernel<<<N_GRAPHS, 256>>>(snn_x, snn_w1, snn_b1);

    // 7 GraphConv layers: ping-pong B -> A -> B -> ... ends in A
    int gemm_blocks = (N_NODES + BM - 1) / BM;
    for (int l = 0; l < N_LAYERS; l++) {
        int in_sel = l & 1;   // 0: read B, write A ; 1: read A, write B
        agg_kernel<<<(N_NODES * 32 + 255) / 256, 256>>>(in_sel);
        gemm_kernel<<<gemm_blocks, 256>>>(in_sel,
            cwrel + (size_t)l * D * D, cwroot + (size_t)l * D * D,
            cbrel + (size_t)l * D);
    }

    // pooling (reads g_bufA)
    count_kernel<<<(N_NODES + 255) / 256, 256>>>(batch);
    pool_kernel<<<(N_NODES + POOL_CHUNK - 1) / POOL_CHUNK, D>>>(batch);

    // heads + fusion
    head_kernel<<<1, N_GRAPHS * N_CLASSES>>>(snn_w2, snn_b2, lin_w, lin_b,
                                             fuse_w, fuse_b, out);
}

// round 9
// speedup vs baseline: 1.2643x; 1.2643x over previous
#include <cuda_runtime.h>
#include <cuda_bf16.h>
#include <stdint.h>

#define N_NODES  100000
#define N_EDGES  1600000
#define D        128
#define N_LAYERS 7
#define N_GRAPHS 64
#define N_CLASSES 10
#define SNN_IN   512
#define SNN_H    1024

// ---------------- device scratch (no allocations allowed) ----------------
__device__ __align__(16) float g_bufA[(size_t)N_NODES * D];
__device__ __align__(16) float g_bufB[(size_t)N_NODES * D];
__device__ __align__(16) float g_agg [(size_t)N_NODES * D];

__device__ int   g_cnt   [N_NODES];
__device__ int   g_rowptr[N_NODES + 1];
__device__ int   g_cursor[N_NODES];
__device__ int   g_col   [N_EDGES];

__device__ float g_pool[N_GRAPHS * D];
__device__ float g_cnts[N_GRAPHS];
__device__ float g_snnh[N_GRAPHS * SNN_H];

__device__ int   g_is64;   // 1 if index inputs are int64, 0 if int32

// ---------------- dtype detection ----------------
__global__ void detect_kernel(const int* __restrict__ ei32) {
    if (threadIdx.x == 0 && blockIdx.x == 0) {
        int orr = 0;
        #pragma unroll 8
        for (int i = 1; i < 256; i += 2) orr |= ei32[i];
        g_is64 = (orr == 0) ? 1 : 0;
    }
}

__device__ __forceinline__ int idx_at(const void* __restrict__ p, long long i, int is64) {
    long long v = is64 ? ((const long long*)p)[i] : (long long)((const int*)p)[i];
    return (int)v;
}
__device__ __forceinline__ int clampi(int v, int lo, int hi) {
    return v < lo ? lo : (v > hi ? hi : v);
}

// ---------------- CSR build ----------------
__global__ void zero_kernel() {
    int i = blockIdx.x * blockDim.x + threadIdx.x;
    if (i < N_NODES) g_cnt[i] = 0;
    if (i < N_GRAPHS * D) g_pool[i] = 0.f;
    if (i < N_GRAPHS) g_cnts[i] = 0.f;
}

__global__ void hist_kernel(const void* __restrict__ ei) {
    int e = blockIdx.x * blockDim.x + threadIdx.x;
    if (e >= N_EDGES) return;
    int is64 = g_is64;
    int dst = clampi(idx_at(ei, (long long)N_EDGES + e, is64), 0, N_NODES - 1);
    atomicAdd(&g_cnt[dst], 1);
}

__global__ void scan_kernel() {
    __shared__ int sh[1024];
    __shared__ int s_carry;
    int tid = threadIdx.x;
    if (tid == 0) { s_carry = 0; g_rowptr[0] = 0; }
    __syncthreads();
    for (int base = 0; base < N_NODES; base += 1024) {
        int i = base + tid;
        int v = (i < N_NODES) ? g_cnt[i] : 0;
        sh[tid] = v;
        __syncthreads();
        for (int off = 1; off < 1024; off <<= 1) {
            int t = (tid >= off) ? sh[tid - off] : 0;
            __syncthreads();
            sh[tid] += t;
            __syncthreads();
        }
        int incl  = sh[tid];
        int carry = s_carry;
        if (i < N_NODES) {
            g_cursor[i]     = carry + incl - v;
            g_rowptr[i + 1] = carry + incl;
        }
        __syncthreads();
        if (tid == 0) s_carry = carry + sh[1023];
        __syncthreads();
    }
}

__global__ void scatter_kernel(const void* __restrict__ ei) {
    int e = blockIdx.x * blockDim.x + threadIdx.x;
    if (e >= N_EDGES) return;
    int is64 = g_is64;
    int src = clampi(idx_at(ei, e, is64),                      0, N_NODES - 1);
    int dst = clampi(idx_at(ei, (long long)N_EDGES + e, is64), 0, N_NODES - 1);
    int pos = atomicAdd(&g_cursor[dst], 1);
    if (pos >= 0 && pos < N_EDGES) g_col[pos] = src;
}

// ---------------- aggregation: warp per node, float4 per lane ----------------
// sel: 2 -> x, 1 -> g_bufA, 0 -> g_bufB
__global__ void agg_kernel(int sel, const float* __restrict__ x) {
    const float* __restrict__ h = (sel == 2) ? x : (sel == 1 ? g_bufA : g_bufB);
    int warp = (blockIdx.x * blockDim.x + threadIdx.x) >> 5;
    int lane = threadIdx.x & 31;
    if (warp >= N_NODES) return;
    int s = g_rowptr[warp];
    int e = g_rowptr[warp + 1];
    float4 acc = make_float4(0.f, 0.f, 0.f, 0.f);
    for (int i = s; i < e; i++) {
        int src = g_col[i];
        float4 v = *(const float4*)(h + (size_t)src * D + lane * 4);
        acc.x += v.x; acc.y += v.y; acc.z += v.z; acc.w += v.w;
    }
    *(float4*)(g_agg + (size_t)warp * D + lane * 4) = acc;
}

// ================= mma.sync bf16x3 GraphConv GEMM =================
// out = relu([agg | h] @ [Wrel ; Wroot] + brel)
// CTA: 256 thr / 8 warps, tile M=128 N=128; warp tile 32x64.
// K=256 in 4 chunks of 64; operands split hi/lo bf16; hh+hl+lh into fp32.

#define APITCH 144              // (64+8) bf16 * 2 bytes, padded row
#define ABUF   18432            // 128 * 144
#define GT_SMEM_BYTES (4 * ABUF)   // Ahi, Alo, Bhi, Blo

__device__ __forceinline__ void mma16816(float* c,
    uint32_t a0, uint32_t a1, uint32_t a2, uint32_t a3,
    uint32_t b0, uint32_t b1)
{
    asm volatile(
        "mma.sync.aligned.m16n8k16.row.col.f32.bf16.bf16.f32 "
        "{%0,%1,%2,%3}, {%4,%5,%6,%7}, {%8,%9}, {%0,%1,%2,%3};"
        : "+f"(c[0]), "+f"(c[1]), "+f"(c[2]), "+f"(c[3])
        : "r"(a0), "r"(a1), "r"(a2), "r"(a3), "r"(b0), "r"(b1));
}

__device__ __forceinline__ uint32_t bf2pack(float a, float b) {
    __nv_bfloat162 t = __float22bfloat162_rn(make_float2(a, b));
    return *(uint32_t*)&t;
}

__global__ __launch_bounds__(256) void gemm_tc(
    int sel, const float* __restrict__ x,
    const float* __restrict__ wrel, const float* __restrict__ wroot,
    const float* __restrict__ brel)
{
    extern __shared__ char sm[];
    char* pAhi = sm;
    char* pAlo = sm + ABUF;
    char* pBhi = sm + 2 * ABUF;
    char* pBlo = sm + 3 * ABUF;

    const float* __restrict__ cur = (sel == 2) ? x : (sel == 1 ? g_bufA : g_bufB);
    float* __restrict__ outp      = (sel == 1) ? g_bufB : g_bufA;

    int tid  = threadIdx.x;
    int lane = tid & 31, wid = tid >> 5;
    int wm = wid & 3, wn = wid >> 2;           // warp grid 4(M) x 2(N)
    int l4 = lane >> 2, l2 = (lane & 3) * 2;   // fragment coords
    int m0 = blockIdx.x * 128;

    float acc[2][8][4];
    #pragma unroll
    for (int a = 0; a < 2; a++)
        #pragma unroll
        for (int t = 0; t < 8; t++)
            #pragma unroll
            for (int j = 0; j < 4; j++) acc[a][t][j] = 0.f;

    for (int c = 0; c < 4; c++) {
        // ---- stage A chunk: 128 rows x 64 cols fp32 -> hi/lo bf16 ----
        const float* __restrict__ asrc = (c < 2) ? g_agg : cur;
        int coff = (c & 1) * 64;
        #pragma unroll
        for (int i = 0; i < 8; i++) {
            int f = tid + i * 256;            // 2048 float4s
            int row = f >> 4, q = f & 15;
            int m = m0 + row;
            float4 v = make_float4(0.f, 0.f, 0.f, 0.f);
            if (m < N_NODES) v = *(const float4*)(asrc + (size_t)m * D + coff + q * 4);
            uint32_t h01 = bf2pack(v.x, v.y), h23 = bf2pack(v.z, v.w);
            float r0 = v.x - __bfloat162float(((__nv_bfloat162*)&h01)->x);
            float r1 = v.y - __bfloat162float(((__nv_bfloat162*)&h01)->y);
            float r2 = v.z - __bfloat162float(((__nv_bfloat162*)&h23)->x);
            float r3 = v.w - __bfloat162float(((__nv_bfloat162*)&h23)->y);
            uint32_t off = (uint32_t)(row * APITCH + q * 8);
            *(uint2*)(pAhi + off) = make_uint2(h01, h23);
            *(uint2*)(pAlo + off) = make_uint2(bf2pack(r0, r1), bf2pack(r2, r3));
        }
        // ---- stage B chunk: [n][k] layout, 128 n x 64 k, hi/lo ----
        const float* __restrict__ wsrc = (c < 2) ? wrel : wroot;
        int k0 = (c & 1) * 64;
        int n = tid & 127;
        int kb = (tid >> 7) * 32;             // half-threads split k range
        #pragma unroll
        for (int k = 0; k < 32; k += 8) {
            float w_[8];
            #pragma unroll
            for (int j = 0; j < 8; j++) w_[j] = wsrc[(size_t)(k0 + kb + k + j) * D + n];
            uint32_t hi[4], lo[4];
            #pragma unroll
            for (int j2 = 0; j2 < 4; j2++) {
                float a = w_[2 * j2], b = w_[2 * j2 + 1];
                uint32_t h = bf2pack(a, b);
                hi[j2] = h;
                lo[j2] = bf2pack(a - __bfloat162float(((__nv_bfloat162*)&h)->x),
                                 b - __bfloat162float(((__nv_bfloat162*)&h)->y));
            }
            uint32_t off = (uint32_t)(n * APITCH + (kb + k) * 2);
            *(uint4*)(pBhi + off) = make_uint4(hi[0], hi[1], hi[2], hi[3]);
            *(uint4*)(pBlo + off) = make_uint4(lo[0], lo[1], lo[2], lo[3]);
        }
        __syncthreads();

        // ---- mainloop: 4 k-steps of 16, 3 splits ----
        #pragma unroll
        for (int ks = 0; ks < 64; ks += 16) {
            uint32_t ah[2][4], al[2][4];
            #pragma unroll
            for (int mt = 0; mt < 2; mt++) {
                int r0 = wm * 32 + mt * 16 + l4;
                int cby = (ks + l2) * 2;
                ah[mt][0] = *(uint32_t*)(pAhi + r0 * APITCH + cby);
                ah[mt][1] = *(uint32_t*)(pAhi + (r0 + 8) * APITCH + cby);
                ah[mt][2] = *(uint32_t*)(pAhi + r0 * APITCH + cby + 16);
                ah[mt][3] = *(uint32_t*)(pAhi + (r0 + 8) * APITCH + cby + 16);
                al[mt][0] = *(uint32_t*)(pAlo + r0 * APITCH + cby);
                al[mt][1] = *(uint32_t*)(pAlo + (r0 + 8) * APITCH + cby);
                al[mt][2] = *(uint32_t*)(pAlo + r0 * APITCH + cby + 16);
                al[mt][3] = *(uint32_t*)(pAlo + (r0 + 8) * APITCH + cby + 16);
            }
            #pragma unroll
            for (int t = 0; t < 8; t++) {
                int n = wn * 64 + t * 8 + l4;
                uint32_t boff = (uint32_t)(n * APITCH + (ks + l2) * 2);
                uint32_t bh0 = *(uint32_t*)(pBhi + boff);
                uint32_t bh1 = *(uint32_t*)(pBhi + boff + 16);
                uint32_t bl0 = *(uint32_t*)(pBlo + boff);
                uint32_t bl1 = *(uint32_t*)(pBlo + boff + 16);
                #pragma unroll
                for (int mt = 0; mt < 2; mt++) {
                    mma16816(acc[mt][t], ah[mt][0], ah[mt][1], ah[mt][2], ah[mt][3], bh0, bh1);
                    mma16816(acc[mt][t], ah[mt][0], ah[mt][1], ah[mt][2], ah[mt][3], bl0, bl1);
                    mma16816(acc[mt][t], al[mt][0], al[mt][1], al[mt][2], al[mt][3], bh0, bh1);
                }
            }
        }
        __syncthreads();
    }

    // ---- epilogue: bias + relu -> fp32 out ----
    #pragma unroll
    for (int mt = 0; mt < 2; mt++) {
        int row = m0 + wm * 32 + mt * 16 + l4;
        #pragma unroll
        for (int t = 0; t < 8; t++) {
            int col = wn * 64 + t * 8 + l2;
            float2 bb = *(const float2*)(brel + col);
            if (row < N_NODES) {
                float2 o0;
                o0.x = fmaxf(acc[mt][t][0] + bb.x, 0.f);
                o0.y = fmaxf(acc[mt][t][1] + bb.y, 0.f);
                *(float2*)(outp + (size_t)row * D + col) = o0;
            }
            if (row + 8 < N_NODES) {
                float2 o1;
                o1.x = fmaxf(acc[mt][t][2] + bb.x, 0.f);
                o1.y = fmaxf(acc[mt][t][3] + bb.y, 0.f);
                *(float2*)(outp + (size_t)(row + 8) * D + col) = o1;
            }
        }
    }
}

// ---------------- pooling ----------------
#define POOL_CHUNK 512
__global__ void pool_kernel(const void* __restrict__ batch) {
    const float* __restrict__ h = g_bufA;   // final h after layer 6
    int ch = threadIdx.x;                   // 128
    int start = blockIdx.x * POOL_CHUNK;
    if (start >= N_NODES) return;
    int end = min(start + POOL_CHUNK, N_NODES);
    int is64 = g_is64;
    int cur = clampi(idx_at(batch, start, is64), 0, N_GRAPHS - 1);
    float acc = 0.f;
    for (int i = start; i < end; i++) {
        int b = clampi(idx_at(batch, i, is64), 0, N_GRAPHS - 1);
        if (b != cur) {
            atomicAdd(&g_pool[cur * D + ch], acc);
            acc = 0.f; cur = b;
        }
        acc += h[(size_t)i * D + ch];
    }
    atomicAdd(&g_pool[cur * D + ch], acc);
}

__global__ void count_kernel(const void* __restrict__ batch) {
    int i = blockIdx.x * blockDim.x + threadIdx.x;
    if (i >= N_NODES) return;
    int b = clampi(idx_at(batch, i, g_is64), 0, N_GRAPHS - 1);
    atomicAdd(&g_cnts[b], 1.f);
}

// ---------------- SNN layer 1 ----------------
__global__ void snn1_kernel(const float* __restrict__ x, const float* __restrict__ w1,
                            const float* __restrict__ b1) {
    __shared__ float xs[SNN_IN];
    int g = blockIdx.x;
    for (int i = threadIdx.x; i < SNN_IN; i += 256) xs[i] = x[g * SNN_IN + i];
    __syncthreads();
    #pragma unroll
    for (int j = 0; j < 4; j++) {
        int n = threadIdx.x + j * 256;
        float acc = b1[n];
        for (int k = 0; k < SNN_IN; k++)
            acc = fmaf(xs[k], w1[(size_t)k * SNN_H + n], acc);
        g_snnh[g * SNN_H + n] = fmaxf(acc, 0.f);
    }
}

// ---------------- final head + fusion ----------------
__global__ void head_kernel(const float* __restrict__ w2, const float* __restrict__ b2,
                            const float* __restrict__ linw, const float* __restrict__ linb,
                            const float* __restrict__ fw, const float* __restrict__ fb,
                            float* __restrict__ out) {
    __shared__ float s_snn[N_GRAPHS * N_CLASSES];
    __shared__ float s_gnn[N_GRAPHS * N_CLASSES];
    int t = threadIdx.x;                // 640
    int g = t / N_CLASSES, c = t % N_CLASSES;

    float acc = b2[c];
    for (int k = 0; k < SNN_H; k++)
        acc = fmaf(g_snnh[g * SNN_H + k], w2[k * N_CLASSES + c], acc);
    s_snn[g * N_CLASSES + c] = 0.85f * acc;

    float cnt = fmaxf(g_cnts[g], 1.0f);
    float inv = 1.0f / cnt;
    float acc2 = linb[c];
    for (int k = 0; k < D; k++)
        acc2 = fmaf(g_pool[g * D + k] * inv, linw[k * N_CLASSES + c], acc2);
    s_gnn[g * N_CLASSES + c] = acc2;
    __syncthreads();

    float o = fb[c];
    #pragma unroll
    for (int j = 0; j < N_CLASSES; j++) {
        o = fmaf(s_snn[g * N_CLASSES + j], fw[j * N_CLASSES + c], o);
        o = fmaf(s_gnn[g * N_CLASSES + j], fw[(N_CLASSES + j) * N_CLASSES + c], o);
    }
    out[g * N_CLASSES + c] = o;
}

// ---------------- launch ----------------
extern "C" void kernel_launch(void* const* d_in, const int* in_sizes, int n_in,
                              void* d_out, int out_size) {
    const float* snn_x  = (const float*)d_in[0];
    const float* x      = (const float*)d_in[1];
    const void*  ei     = d_in[2];
    const void*  batch  = d_in[3];
    const float* snn_w1 = (const float*)d_in[4];
    const float* snn_b1 = (const float*)d_in[5];
    const float* snn_w2 = (const float*)d_in[6];
    const float* snn_b2 = (const float*)d_in[7];
    const float* cwrel  = (const float*)d_in[8];
    const float* cwroot = (const float*)d_in[9];
    const float* cbrel  = (const float*)d_in[10];
    const float* lin_w  = (const float*)d_in[11];
    const float* lin_b  = (const float*)d_in[12];
    const float* fuse_w = (const float*)d_in[13];
    const float* fuse_b = (const float*)d_in[14];
    float* out = (float*)d_out;

    // opt into >48KB dynamic smem for the GEMM (function attribute, capture-safe)
    cudaFuncSetAttribute(gemm_tc, cudaFuncAttributeMaxDynamicSharedMemorySize,
                         GT_SMEM_BYTES);

    // dtype detection + CSR build + zeroing
    detect_kernel<<<1, 32>>>((const int*)ei);
    zero_kernel<<<(N_NODES + 255) / 256, 256>>>();
    hist_kernel<<<(N_EDGES + 255) / 256, 256>>>(ei);
    scan_kernel<<<1, 1024>>>();
    scatter_kernel<<<(N_EDGES + 255) / 256, 256>>>(ei);

    // SNN branch (independent)
    snn1_kernel<<<N_GRAPHS, 256>>>(snn_x, snn_w1, snn_b1);

    // 7 GraphConv layers: x -> A -> B -> A -> ... ends in A
    int gemm_blocks = (N_NODES + 127) / 128;
    for (int l = 0; l < N_LAYERS; l++) {
        int sel = (l == 0) ? 2 : (l & 1);   // 2: x->A, 1: A->B, 0: B->A
        agg_kernel<<<(N_NODES * 32 + 255) / 256, 256>>>(sel, x);
        gemm_tc<<<gemm_blocks, 256, GT_SMEM_BYTES>>>(sel, x,
            cwrel + (size_t)l * D * D, cwroot + (size_t)l * D * D,
            cbrel + (size_t)l * D);
    }

    // pooling (reads g_bufA)
    count_kernel<<<(N_NODES + 255) / 256, 256>>>(batch);
    pool_kernel<<<(N_NODES + POOL_CHUNK - 1) / POOL_CHUNK, D>>>(batch);

    // heads + fusion
    head_kernel<<<1, N_GRAPHS * N_CLASSES>>>(snn_w2, snn_b2, lin_w, lin_b,
                                             fuse_w, fuse_b, out);
}

// round 10
// speedup vs baseline: 1.3156x; 1.0406x over previous
#include <cuda_runtime.h>
#include <cuda_bf16.h>
#include <stdint.h>

#define N_NODES  100000
#define N_EDGES  1600000
#define D        128
#define N_LAYERS 7
#define N_GRAPHS 64
#define N_CLASSES 10
#define SNN_IN   512
#define SNN_H    1024

typedef __nv_bfloat16 bf16;

// ---------------- device scratch (no allocations allowed) ----------------
// node features stored as hi/lo bf16 pairs (fp32-equivalent: err ~2^-17)
__device__ __align__(16) bf16 g_xH [(size_t)N_NODES * D];
__device__ __align__(16) bf16 g_xL [(size_t)N_NODES * D];
__device__ __align__(16) bf16 g_hAH[(size_t)N_NODES * D];
__device__ __align__(16) bf16 g_hAL[(size_t)N_NODES * D];
__device__ __align__(16) bf16 g_hBH[(size_t)N_NODES * D];
__device__ __align__(16) bf16 g_hBL[(size_t)N_NODES * D];
__device__ __align__(16) bf16 g_agH[(size_t)N_NODES * D];
__device__ __align__(16) bf16 g_agL[(size_t)N_NODES * D];

// pre-split weights, [layer][rel/root][n=128][k=128]
__device__ __align__(16) bf16 g_wH[N_LAYERS * 2 * D * D];
__device__ __align__(16) bf16 g_wL[N_LAYERS * 2 * D * D];

__device__ int   g_cnt   [N_NODES];
__device__ int   g_rowptr[N_NODES + 1];
__device__ int   g_cursor[N_NODES];
__device__ int   g_col   [N_EDGES];

__device__ float g_pool[N_GRAPHS * D];
__device__ float g_cnts[N_GRAPHS];
__device__ float g_snnh[N_GRAPHS * SNN_H];

__device__ int   g_is64;

// ---------------- small helpers ----------------
__device__ __forceinline__ uint32_t bf2pack(float a, float b) {
    __nv_bfloat162 t = __float22bfloat162_rn(make_float2(a, b));
    return *(uint32_t*)&t;
}
__device__ __forceinline__ int idx_at(const void* __restrict__ p, long long i, int is64) {
    long long v = is64 ? ((const long long*)p)[i] : (long long)((const int*)p)[i];
    return (int)v;
}
__device__ __forceinline__ int clampi(int v, int lo, int hi) {
    return v < lo ? lo : (v > hi ? hi : v);
}
__device__ __forceinline__ uint32_t smem_u32(const void* p) {
    uint32_t a;
    asm("{ .reg .u64 t; cvta.to.shared.u64 t, %1; cvt.u32.u64 %0, t; }" : "=r"(a) : "l"(p));
    return a;
}
__device__ __forceinline__ void cp16(uint32_t dst, const void* src) {
    asm volatile("cp.async.cg.shared.global [%0], [%1], 16;" :: "r"(dst), "l"(src));
}
#define CP_COMMIT asm volatile("cp.async.commit_group;" ::: "memory")
#define CP_WAIT0  asm volatile("cp.async.wait_group 0;"  ::: "memory")

// ---------------- dtype detection ----------------
__global__ void detect_kernel(const int* __restrict__ ei32) {
    if (threadIdx.x == 0 && blockIdx.x == 0) {
        int orr = 0;
        #pragma unroll 8
        for (int i = 1; i < 256; i += 2) orr |= ei32[i];
        g_is64 = (orr == 0) ? 1 : 0;
    }
}

// ---------------- x -> hi/lo bf16 ----------------
__global__ void xconv_kernel(const float* __restrict__ x) {
    size_t i = (size_t)blockIdx.x * blockDim.x + threadIdx.x;
    size_t n4 = (size_t)N_NODES * D / 4;
    if (i >= n4) return;
    float4 v = ((const float4*)x)[i];
    uint32_t h01 = bf2pack(v.x, v.y), h23 = bf2pack(v.z, v.w);
    float r0 = v.x - __bfloat162float(((__nv_bfloat162*)&h01)->x);
    float r1 = v.y - __bfloat162float(((__nv_bfloat162*)&h01)->y);
    float r2 = v.z - __bfloat162float(((__nv_bfloat162*)&h23)->x);
    float r3 = v.w - __bfloat162float(((__nv_bfloat162*)&h23)->y);
    ((uint2*)g_xH)[i] = make_uint2(h01, h23);
    ((uint2*)g_xL)[i] = make_uint2(bf2pack(r0, r1), bf2pack(r2, r3));
}

// ---------------- weight pre-split: [l][s][n][k] ----------------
__global__ void wprep_kernel(const float* __restrict__ cwrel,
                             const float* __restrict__ cwroot) {
    int b = blockIdx.x;                 // l*256 + s*128 + k
    int l = b >> 8, s = (b >> 7) & 1, k = b & 127;
    int n = threadIdx.x;
    const float* w = (s ? cwroot : cwrel) + (size_t)l * D * D;
    float v = w[k * D + n];
    bf16 h = __float2bfloat16(v);
    float r = v - __bfloat162float(h);
    size_t o = ((size_t)(l * 2 + s) * D + n) * D + k;
    g_wH[o] = h;
    g_wL[o] = __float2bfloat16(r);
}

// ---------------- CSR build ----------------
__global__ void zero_kernel() {
    int i = blockIdx.x * blockDim.x + threadIdx.x;
    if (i < N_NODES) g_cnt[i] = 0;
    if (i < N_GRAPHS * D) g_pool[i] = 0.f;
    if (i < N_GRAPHS) g_cnts[i] = 0.f;
}

__global__ void hist_kernel(const void* __restrict__ ei) {
    int e = blockIdx.x * blockDim.x + threadIdx.x;
    if (e >= N_EDGES) return;
    int dst = clampi(idx_at(ei, (long long)N_EDGES + e, g_is64), 0, N_NODES - 1);
    atomicAdd(&g_cnt[dst], 1);
}

// single-block scan, 4 elems/thread, warp-shuffle based (few barriers)
__global__ void scan_kernel() {
    __shared__ int wsum[32];
    __shared__ int s_carry;
    int tid = threadIdx.x, lane = tid & 31, wid = tid >> 5;
    if (tid == 0) { s_carry = 0; g_rowptr[0] = 0; }
    __syncthreads();
    for (int base = 0; base < N_NODES; base += 4096) {
        int i0 = base + tid * 4;
        int v0 = 0, v1 = 0, v2 = 0, v3 = 0;
        if (i0 + 3 < N_NODES) {
            int4 v = *(const int4*)&g_cnt[i0];
            v0 = v.x; v1 = v.y; v2 = v.z; v3 = v.w;
        } else if (i0 < N_NODES) {
            v0 = g_cnt[i0];
            if (i0 + 1 < N_NODES) v1 = g_cnt[i0 + 1];
            if (i0 + 2 < N_NODES) v2 = g_cnt[i0 + 2];
        }
        int s0 = v0, s1 = s0 + v1, s2 = s1 + v2, s3 = s2 + v3;
        // warp inclusive scan of per-thread totals
        int t = s3;
        #pragma unroll
        for (int off = 1; off < 32; off <<= 1) {
            int u = __shfl_up_sync(0xFFFFFFFFu, t, off);
            if (lane >= off) t += u;
        }
        if (lane == 31) wsum[wid] = t;
        __syncthreads();
        if (wid == 0) {
            int w = wsum[lane];
            #pragma unroll
            for (int off = 1; off < 32; off <<= 1) {
                int u = __shfl_up_sync(0xFFFFFFFFu, w, off);
                if (lane >= off) w += u;
            }
            wsum[lane] = w;
        }
        __syncthreads();
        int warpoff = (wid > 0) ? wsum[wid - 1] : 0;
        int throff = s_carry + warpoff + (t - s3);   // exclusive prefix of elem i0
        if (i0 < N_NODES)     { g_cursor[i0]     = throff;      g_rowptr[i0 + 1] = throff + s0; }
        if (i0 + 1 < N_NODES) { g_cursor[i0 + 1] = throff + s0; g_rowptr[i0 + 2] = throff + s1; }
        if (i0 + 2 < N_NODES) { g_cursor[i0 + 2] = throff + s1; g_rowptr[i0 + 3] = throff + s2; }
        if (i0 + 3 < N_NODES) { g_cursor[i0 + 3] = throff + s2; g_rowptr[i0 + 4] = throff + s3; }
        int tot = wsum[31];
        __syncthreads();
        if (tid == 0) s_carry += tot;
        __syncthreads();
    }
}

__global__ void scatter_kernel(const void* __restrict__ ei) {
    int e = blockIdx.x * blockDim.x + threadIdx.x;
    if (e >= N_EDGES) return;
    int is64 = g_is64;
    int src = clampi(idx_at(ei, e, is64),                      0, N_NODES - 1);
    int dst = clampi(idx_at(ei, (long long)N_EDGES + e, is64), 0, N_NODES - 1);
    int pos = atomicAdd(&g_cursor[dst], 1);
    if (pos >= 0 && pos < N_EDGES) g_col[pos] = src;
}

// ---------------- aggregation: warp per node, hi/lo in, hi/lo out ----------
// sel: 2 -> x, 1 -> bufA, 0 -> bufB
__global__ void agg_kernel(int sel) {
    const bf16* __restrict__ H = (sel == 2) ? g_xH : (sel == 1 ? g_hAH : g_hBH);
    const bf16* __restrict__ L = (sel == 2) ? g_xL : (sel == 1 ? g_hAL : g_hBL);
    int warp = (blockIdx.x * blockDim.x + threadIdx.x) >> 5;
    int lane = threadIdx.x & 31;
    if (warp >= N_NODES) return;
    int s = g_rowptr[warp];
    int e = g_rowptr[warp + 1];
    float4 acc = make_float4(0.f, 0.f, 0.f, 0.f);
    for (int i = s; i < e; i++) {
        int src = g_col[i];
        uint2 hv = *(const uint2*)(H + (size_t)src * D + lane * 4);
        uint2 lv = *(const uint2*)(L + (size_t)src * D + lane * 4);
        float2 a0 = __bfloat1622float2(*(__nv_bfloat162*)&hv.x);
        float2 a1 = __bfloat1622float2(*(__nv_bfloat162*)&hv.y);
        float2 b0 = __bfloat1622float2(*(__nv_bfloat162*)&lv.x);
        float2 b1 = __bfloat1622float2(*(__nv_bfloat162*)&lv.y);
        acc.x += a0.x + b0.x; acc.y += a0.y + b0.y;
        acc.z += a1.x + b1.x; acc.w += a1.y + b1.y;
    }
    uint32_t h01 = bf2pack(acc.x, acc.y), h23 = bf2pack(acc.z, acc.w);
    float r0 = acc.x - __bfloat162float(((__nv_bfloat162*)&h01)->x);
    float r1 = acc.y - __bfloat162float(((__nv_bfloat162*)&h01)->y);
    float r2 = acc.z - __bfloat162float(((__nv_bfloat162*)&h23)->x);
    float r3 = acc.w - __bfloat162float(((__nv_bfloat162*)&h23)->y);
    size_t o = (size_t)warp * D + lane * 4;
    *(uint2*)(g_agH + o) = make_uint2(h01, h23);
    *(uint2*)(g_agL + o) = make_uint2(bf2pack(r0, r1), bf2pack(r2, r3));
}

// ================= mma.sync bf16x3 GraphConv GEMM =================
// CTA: 256 thr / 8 warps, tile M=128 N=128; warp tile 32x64.
// K=256 in 4 chunks of 64; all staging via cp.async (data pre-split hi/lo).

#define APITCH 144              // (64+8) bf16 * 2 bytes, padded row
#define ABUF   18432            // 128 * 144
#define GT_SMEM_BYTES (4 * ABUF)   // Ahi, Alo, Bhi, Blo (one stage, 72KB)

__device__ __forceinline__ void mma16816(float* c,
    uint32_t a0, uint32_t a1, uint32_t a2, uint32_t a3,
    uint32_t b0, uint32_t b1)
{
    asm volatile(
        "mma.sync.aligned.m16n8k16.row.col.f32.bf16.bf16.f32 "
        "{%0,%1,%2,%3}, {%4,%5,%6,%7}, {%8,%9}, {%0,%1,%2,%3};"
        : "+f"(c[0]), "+f"(c[1]), "+f"(c[2]), "+f"(c[3])
        : "r"(a0), "r"(a1), "r"(a2), "r"(a3), "r"(b0), "r"(b1));
}

__global__ __launch_bounds__(256) void gemm_tc(int sel, int layer,
                                               const float* __restrict__ brel)
{
    extern __shared__ char sm[];
    char* pAhi = sm;
    char* pAlo = sm + ABUF;
    char* pBhi = sm + 2 * ABUF;
    char* pBlo = sm + 3 * ABUF;
    uint32_t sb32 = smem_u32(sm);

    const bf16* __restrict__ curH = (sel == 2) ? g_xH : (sel == 1 ? g_hAH : g_hBH);
    const bf16* __restrict__ curL = (sel == 2) ? g_xL : (sel == 1 ? g_hAL : g_hBL);
    bf16* __restrict__ outH = (sel == 1) ? g_hBH : g_hAH;
    bf16* __restrict__ outL = (sel == 1) ? g_hBL : g_hAL;
    const bf16* __restrict__ wHb = g_wH + (size_t)layer * 2 * D * D;
    const bf16* __restrict__ wLb = g_wL + (size_t)layer * 2 * D * D;

    int tid  = threadIdx.x;
    int lane = tid & 31, wid = tid >> 5;
    int wm = wid & 3, wn = wid >> 2;           // warp grid 4(M) x 2(N)
    int l4 = lane >> 2, l2 = (lane & 3) * 2;
    int m0 = blockIdx.x * 128;

    float acc[2][8][4];
    #pragma unroll
    for (int a = 0; a < 2; a++)
        #pragma unroll
        for (int t = 0; t < 8; t++)
            #pragma unroll
            for (int j = 0; j < 4; j++) acc[a][t][j] = 0.f;

    #pragma unroll 1
    for (int c = 0; c < 4; c++) {
        // ---- stage chunk c: 4096 x 16B cp.async, 16 per thread ----
        const bf16* aH = (c < 2) ? g_agH : curH;
        const bf16* aL = (c < 2) ? g_agL : curL;
        int acoff = (c & 1) * 64;
        const bf16* wH = wHb + (c < 2 ? 0 : D * D);
        const bf16* wL = wLb + (c < 2 ? 0 : D * D);
        int k0 = (c & 1) * 64;

        #pragma unroll
        for (int i = 0; i < 16; i++) {
            const int arr = i >> 2;                 // compile-time: 0 AH,1 AL,2 BH,3 BL
            int cid = (i & 3) * 256 + tid;          // 0..1023
            int row = cid >> 3, ch = cid & 7;
            uint32_t dst = sb32 + arr * ABUF + row * APITCH + ch * 16;
            if (arr < 2) {
                int m = m0 + row; if (m >= N_NODES) m = 0;
                const bf16* bp = (arr == 0) ? aH : aL;
                cp16(dst, bp + (size_t)m * D + acoff + ch * 8);
            } else {
                const bf16* bp = (arr == 2) ? wH : wL;
                cp16(dst, bp + (size_t)row * D + k0 + ch * 8);
            }
        }
        CP_COMMIT;
        CP_WAIT0;
        __syncthreads();

        // ---- mainloop: 4 k-steps of 16, 3 splits (hh, hl, lh) ----
        #pragma unroll
        for (int ks = 0; ks < 64; ks += 16) {
            uint32_t ah[2][4], al[2][4];
            #pragma unroll
            for (int mt = 0; mt < 2; mt++) {
                int r0 = wm * 32 + mt * 16 + l4;
                int cby = (ks + l2) * 2;
                ah[mt][0] = *(uint32_t*)(pAhi + r0 * APITCH + cby);
                ah[mt][1] = *(uint32_t*)(pAhi + (r0 + 8) * APITCH + cby);
                ah[mt][2] = *(uint32_t*)(pAhi + r0 * APITCH + cby + 16);
                ah[mt][3] = *(uint32_t*)(pAhi + (r0 + 8) * APITCH + cby + 16);
                al[mt][0] = *(uint32_t*)(pAlo + r0 * APITCH + cby);
                al[mt][1] = *(uint32_t*)(pAlo + (r0 + 8) * APITCH + cby);
                al[mt][2] = *(uint32_t*)(pAlo + r0 * APITCH + cby + 16);
                al[mt][3] = *(uint32_t*)(pAlo + (r0 + 8) * APITCH + cby + 16);
            }
            #pragma unroll
            for (int t = 0; t < 8; t++) {
                int n = wn * 64 + t * 8 + l4;
                uint32_t boff = (uint32_t)(n * APITCH + (ks + l2) * 2);
                uint32_t bh0 = *(uint32_t*)(pBhi + boff);
                uint32_t bh1 = *(uint32_t*)(pBhi + boff + 16);
                uint32_t bl0 = *(uint32_t*)(pBlo + boff);
                uint32_t bl1 = *(uint32_t*)(pBlo + boff + 16);
                #pragma unroll
                for (int mt = 0; mt < 2; mt++) {
                    mma16816(acc[mt][t], ah[mt][0], ah[mt][1], ah[mt][2], ah[mt][3], bh0, bh1);
                    mma16816(acc[mt][t], ah[mt][0], ah[mt][1], ah[mt][2], ah[mt][3], bl0, bl1);
                    mma16816(acc[mt][t], al[mt][0], al[mt][1], al[mt][2], al[mt][3], bh0, bh1);
                }
            }
        }
        __syncthreads();
    }

    // ---- epilogue: bias + relu -> hi/lo bf16 out ----
    #pragma unroll
    for (int mt = 0; mt < 2; mt++) {
        int row = m0 + wm * 32 + mt * 16 + l4;
        #pragma unroll
        for (int t = 0; t < 8; t++) {
            int col = wn * 64 + t * 8 + l2;
            float2 bb = *(const float2*)(brel + col);
            #pragma unroll
            for (int h = 0; h < 2; h++) {
                int r = row + h * 8;
                if (r < N_NODES) {
                    float ox = fmaxf(acc[mt][t][h * 2 + 0] + bb.x, 0.f);
                    float oy = fmaxf(acc[mt][t][h * 2 + 1] + bb.y, 0.f);
                    uint32_t hp = bf2pack(ox, oy);
                    float rx = ox - __bfloat162float(((__nv_bfloat162*)&hp)->x);
                    float ry = oy - __bfloat162float(((__nv_bfloat162*)&hp)->y);
                    size_t o = (size_t)r * D + col;
                    *(uint32_t*)(outH + o) = hp;
                    *(uint32_t*)(outL + o) = bf2pack(rx, ry);
                }
            }
        }
    }
}

// ---------------- pooling (reads final h = bufA hi/lo) ----------------
#define POOL_CHUNK 512
__global__ void pool_kernel(const void* __restrict__ batch) {
    int ch = threadIdx.x;                   // 128
    int start = blockIdx.x * POOL_CHUNK;
    if (start >= N_NODES) return;
    int end = min(start + POOL_CHUNK, N_NODES);
    int is64 = g_is64;
    int cur = clampi(idx_at(batch, start, is64), 0, N_GRAPHS - 1);
    float acc = 0.f;
    for (int i = start; i < end; i++) {
        int b = clampi(idx_at(batch, i, is64), 0, N_GRAPHS - 1);
        if (b != cur) {
            atomicAdd(&g_pool[cur * D + ch], acc);
            acc = 0.f; cur = b;
        }
        size_t o = (size_t)i * D + ch;
        acc += __bfloat162float(g_hAH[o]) + __bfloat162float(g_hAL[o]);
    }
    atomicAdd(&g_pool[cur * D + ch], acc);
}

__global__ void count_kernel(const void* __restrict__ batch) {
    int i = blockIdx.x * blockDim.x + threadIdx.x;
    if (i >= N_NODES) return;
    int b = clampi(idx_at(batch, i, g_is64), 0, N_GRAPHS - 1);
    atomicAdd(&g_cnts[b], 1.f);
}

// ---------------- SNN layer 1 ----------------
__global__ void snn1_kernel(const float* __restrict__ x, const float* __restrict__ w1,
                            const float* __restrict__ b1) {
    __shared__ float xs[SNN_IN];
    int g = blockIdx.x;
    for (int i = threadIdx.x; i < SNN_IN; i += 256) xs[i] = x[g * SNN_IN + i];
    __syncthreads();
    #pragma unroll
    for (int j = 0; j < 4; j++) {
        int n = threadIdx.x + j * 256;
        float acc = b1[n];
        for (int k = 0; k < SNN_IN; k++)
            acc = fmaf(xs[k], w1[(size_t)k * SNN_H + n], acc);
        g_snnh[g * SNN_H + n] = fmaxf(acc, 0.f);
    }
}

// ---------------- final head + fusion ----------------
__global__ void head_kernel(const float* __restrict__ w2, const float* __restrict__ b2,
                            const float* __restrict__ linw, const float* __restrict__ linb,
                            const float* __restrict__ fw, const float* __restrict__ fb,
                            float* __restrict__ out) {
    __shared__ float s_snn[N_GRAPHS * N_CLASSES];
    __shared__ float s_gnn[N_GRAPHS * N_CLASSES];
    int t = threadIdx.x;                // 640
    int g = t / N_CLASSES, c = t % N_CLASSES;

    float acc = b2[c];
    for (int k = 0; k < SNN_H; k++)
        acc = fmaf(g_snnh[g * SNN_H + k], w2[k * N_CLASSES + c], acc);
    s_snn[g * N_CLASSES + c] = 0.85f * acc;

    float cnt = fmaxf(g_cnts[g], 1.0f);
    float inv = 1.0f / cnt;
    float acc2 = linb[c];
    for (int k = 0; k < D; k++)
        acc2 = fmaf(g_pool[g * D + k] * inv, linw[k * N_CLASSES + c], acc2);
    s_gnn[g * N_CLASSES + c] = acc2;
    __syncthreads();

    float o = fb[c];
    #pragma unroll
    for (int j = 0; j < N_CLASSES; j++) {
        o = fmaf(s_snn[g * N_CLASSES + j], fw[j * N_CLASSES + c], o);
        o = fmaf(s_gnn[g * N_CLASSES + j], fw[(N_CLASSES + j) * N_CLASSES + c], o);
    }
    out[g * N_CLASSES + c] = o;
}

// ---------------- launch ----------------
extern "C" void kernel_launch(void* const* d_in, const int* in_sizes, int n_in,
                              void* d_out, int out_size) {
    const float* snn_x  = (const float*)d_in[0];
    const float* x      = (const float*)d_in[1];
    const void*  ei     = d_in[2];
    const void*  batch  = d_in[3];
    const float* snn_w1 = (const float*)d_in[4];
    const float* snn_b1 = (const float*)d_in[5];
    const float* snn_w2 = (const float*)d_in[6];
    const float* snn_b2 = (const float*)d_in[7];
    const float* cwrel  = (const float*)d_in[8];
    const float* cwroot = (const float*)d_in[9];
    const float* cbrel  = (const float*)d_in[10];
    const float* lin_w  = (const float*)d_in[11];
    const float* lin_b  = (const float*)d_in[12];
    const float* fuse_w = (const float*)d_in[13];
    const float* fuse_b = (const float*)d_in[14];
    float* out = (float*)d_out;

    cudaFuncSetAttribute(gemm_tc, cudaFuncAttributeMaxDynamicSharedMemorySize,
                         GT_SMEM_BYTES);

    // dtype detection + pre-splits + CSR build
    detect_kernel<<<1, 32>>>((const int*)ei);
    xconv_kernel<<<(N_NODES * D / 4 + 255) / 256, 256>>>(x);
    wprep_kernel<<<N_LAYERS * 256, 128>>>(cwrel, cwroot);
    zero_kernel<<<(N_NODES + 255) / 256, 256>>>();
    hist_kernel<<<(N_EDGES + 255) / 256, 256>>>(ei);
    scan_kernel<<<1, 1024>>>();
    scatter_kernel<<<(N_EDGES + 255) / 256, 256>>>(ei);

    // SNN branch (independent)
    snn1_kernel<<<N_GRAPHS, 256>>>(snn_x, snn_w1, snn_b1);

    // 7 GraphConv layers: x -> A -> B -> A -> ... ends in A
    int gemm_blocks = (N_NODES + 127) / 128;
    for (int l = 0; l < N_LAYERS; l++) {
        int sel = (l == 0) ? 2 : (l & 1);   // 2: x->A, 1: A->B, 0: B->A
        agg_kernel<<<(N_NODES * 32 + 255) / 256, 256>>>(sel);
        gemm_tc<<<gemm_blocks, 256, GT_SMEM_BYTES>>>(sel, l, cbrel + (size_t)l * D);
    }

    // pooling (reads bufA hi/lo)
    count_kernel<<<(N_NODES + 255) / 256, 256>>>(batch);
    pool_kernel<<<(N_NODES + POOL_CHUNK - 1) / POOL_CHUNK, D>>>(batch);

    // heads + fusion
    head_kernel<<<1, N_GRAPHS * N_CLASSES>>>(snn_w2, snn_b2, lin_w, lin_b,
                                             fuse_w, fuse_b, out);
}